// round 7
// baseline (speedup 1.0000x reference)
#include <cuda_runtime.h>

#define BSZ   8
#define NPTS  4096
#define CIN   128
#define COUT  256
#define MCTR  1024
#define SSAMP 64

// Scratch (static device globals: no allocations allowed)
__device__ float  g_pre[BSZ * NPTS * COUT];   // [b][n][o]  33.5 MB
__device__ int    g_fps[BSZ * MCTR];
__device__ int    g_idx[BSZ * MCTR * SSAMP];
__device__ float4 g_sort[BSZ * NPTS];         // Morton-sorted (x,y,z,orig_idx)

// Exact reference arithmetic: squares then left-to-right sum, no FMA contraction.
__device__ __forceinline__ float d2_rn(float ax, float ay, float az,
                                       float bx, float by, float bz) {
    float dx = ax - bx, dy = ay - by, dz = az - bz;
    return __fadd_rn(__fadd_rn(__fmul_rn(dx, dx), __fmul_rn(dy, dy)),
                     __fmul_rn(dz, dz));
}

// ---- packed f32x2 helpers (per-lane IEEE rn: bit-identical to scalar) ----
__device__ __forceinline__ unsigned long long pack2(float lo, float hi) {
    unsigned long long r;
    asm("mov.b64 %0, {%1, %2};" : "=l"(r) : "f"(lo), "f"(hi));
    return r;
}
__device__ __forceinline__ void unpack2(unsigned long long v, float& lo, float& hi) {
    asm("mov.b64 {%0, %1}, %2;" : "=f"(lo), "=f"(hi) : "l"(v));
}
__device__ __forceinline__ unsigned long long add2(unsigned long long a,
                                                   unsigned long long b) {
    unsigned long long r;
    asm("add.rn.f32x2 %0, %1, %2;" : "=l"(r) : "l"(a), "l"(b));
    return r;
}
__device__ __forceinline__ unsigned long long mul2(unsigned long long a,
                                                   unsigned long long b) {
    unsigned long long r;
    asm("mul.rn.f32x2 %0, %1, %2;" : "=l"(r) : "l"(a), "l"(b));
    return r;
}

__device__ __forceinline__ int expand3(int v) {   // 3-bit -> every 3rd bit
    return (v & 1) | ((v & 2) << 2) | ((v & 4) << 4);
}

// ---------------------------------------------------------------------------
// 0) Morton counting-sort per batch: 8x8x8 cells, permutation kept via the
//    original index stored in .w. Order within a cell is irrelevant to the
//    (bit-exact) FPS result — tie-breaks use original indices.
// ---------------------------------------------------------------------------
__global__ __launch_bounds__(512) void sort_kernel(const float* __restrict__ xyz) {
    const int b = blockIdx.x, tid = threadIdx.x;
    const int lane = tid & 31, warp = tid >> 5;
    __shared__ int hist[512];
    __shared__ int wsum[16];
    const float* p = xyz + b * NPTS * 3;

    hist[tid] = 0;
    __syncthreads();

    float x[8], y[8], z[8]; int cell[8];
#pragma unroll
    for (int i = 0; i < 8; i++) {
        int n = tid + i * 512;
        x[i] = p[3 * n + 0]; y[i] = p[3 * n + 1]; z[i] = p[3 * n + 2];
        int cx = min(7, max(0, (int)(x[i] * 8.0f)));
        int cy = min(7, max(0, (int)(y[i] * 8.0f)));
        int cz = min(7, max(0, (int)(z[i] * 8.0f)));
        cell[i] = expand3(cx) | (expand3(cy) << 1) | (expand3(cz) << 2);
        atomicAdd(&hist[cell[i]], 1);
    }
    __syncthreads();

    // block exclusive scan over 512 bins
    int v = hist[tid];
    int inc = v;
#pragma unroll
    for (int o = 1; o < 32; o <<= 1) {
        int t = __shfl_up_sync(0xffffffffu, inc, o);
        if (lane >= o) inc += t;
    }
    if (lane == 31) wsum[warp] = inc;
    __syncthreads();
    if (warp == 0) {
        int t = (lane < 16) ? wsum[lane] : 0;
#pragma unroll
        for (int o = 1; o < 16; o <<= 1) {
            int u = __shfl_up_sync(0xffffffffu, t, o);
            if (lane >= o) t += u;
        }
        if (lane < 16) wsum[lane] = t;   // inclusive warp totals
    }
    __syncthreads();
    int excl = inc - v + ((warp == 0) ? 0 : wsum[warp - 1]);
    hist[tid] = excl;
    __syncthreads();

#pragma unroll
    for (int i = 0; i < 8; i++) {
        int pos = atomicAdd(&hist[cell[i]], 1);
        int n = tid + i * 512;
        g_sort[b * NPTS + pos] = make_float4(x[i], y[i], z[i], __int_as_float(n));
    }
}

// ---------------------------------------------------------------------------
// 1) FPS with exact warp-uniform pruning. 512 threads x 8 SORTED points.
//    Skip condition (|c-cen|^2 > T2, all lanes) provably leaves every mind
//    bit-unchanged (triangle inequality + >=1e-4 multiplicative margins vs
//    ~1e-7 fp rounding), so the update is a no-op and may be skipped.
//    Update path arithmetic is bit-identical to rounds 4-6 (passed).
// ---------------------------------------------------------------------------
__device__ void fps_body(const float* __restrict__ xyz, int b) {
    const int tid = threadIdx.x;
    const int lane = tid & 31, warp = tid >> 5;   // 16 warps

    __shared__ int    s_val[2][16];
    __shared__ int    s_key[2][16];
    __shared__ float4 s_cc[2][16];

    const float* p = xyz + b * NPTS * 3;
    const float4* sp = g_sort + b * NPTS;

    float fx[8], fy[8], fz[8], mind[8]; int o[8];
#pragma unroll
    for (int k = 0; k < 8; k++) {
        float4 v = sp[tid * 8 + k];
        fx[k] = v.x; fy[k] = v.y; fz[k] = v.z;
        o[k] = __float_as_int(v.w);
        mind[k] = 1e10f;
    }
    unsigned long long px2[4], py2[4], pz2[4];
#pragma unroll
    for (int j = 0; j < 4; j++) {
        px2[j] = pack2(fx[2 * j], fx[2 * j + 1]);
        py2[j] = pack2(fy[2 * j], fy[2 * j + 1]);
        pz2[j] = pack2(fz[2 * j], fz[2 * j + 1]);
    }
    // conservative cluster bound: cen = first point, radp >= max |p_k - cen|
    const float cenx = fx[0], ceny = fy[0], cenz = fz[0];
    float r2m = 0.0f;
#pragma unroll
    for (int k = 1; k < 8; k++) {
        float dx = fx[k] - cenx, dy = fy[k] - ceny, dz = fz[k] - cenz;
        r2m = fmaxf(r2m, dx * dx + dy * dy + dz * dz);
    }
    const float radp = sqrtf(r2m) * 1.0001f + 1e-7f;

    float T2 = 3.4e38f;                    // force update on first iteration
    int   tb = __float_as_int(1e10f);      // cached best (max of mind) bits

    float cx = __ldg(p + 0), cy = __ldg(p + 1), cz = __ldg(p + 2);
    if (tid == 0) g_fps[b * MCTR] = 0;

    for (int t = 1; t < MCTR; t++) {
        float qx = cx - cenx, qy = cy - ceny, qz = cz - cenz;
        float q = qx * qx + qy * qy + qz * qz;

        if (!__all_sync(0xffffffffu, q > T2)) {
            const unsigned long long nlx2 = pack2(-cx, -cx);
            const unsigned long long nly2 = pack2(-cy, -cy);
            const unsigned long long nlz2 = pack2(-cz, -cz);
#pragma unroll
            for (int j = 0; j < 4; j++) {
                unsigned long long dx2 = add2(px2[j], nlx2);
                unsigned long long dy2 = add2(py2[j], nly2);
                unsigned long long dz2 = add2(pz2[j], nlz2);
                unsigned long long s2 = add2(add2(mul2(dx2, dx2), mul2(dy2, dy2)),
                                             mul2(dz2, dz2));
                float s0, s1; unpack2(s2, s0, s1);
                mind[2 * j]     = fminf(mind[2 * j],     s0);
                mind[2 * j + 1] = fminf(mind[2 * j + 1], s1);
            }
            float m01 = fmaxf(mind[0], mind[1]), m23 = fmaxf(mind[2], mind[3]);
            float m45 = fmaxf(mind[4], mind[5]), m67 = fmaxf(mind[6], mind[7]);
            float best = fmaxf(fmaxf(m01, m23), fmaxf(m45, m67));
            tb = __float_as_int(best);
            float s = sqrtf(best) * 1.0001f + radp;
            T2 = s * s * 1.0001f;
        }

        const int wmax = __reduce_max_sync(0xffffffffu, tb);
        int key = 0x7fffffff;
        if (tb == wmax) {   // rare; resolve this thread's lowest ORIGINAL idx
            int n = 0x7fffffff;
#pragma unroll
            for (int k = 7; k >= 0; k--)
                if (__float_as_int(mind[k]) == wmax) n = min(n, o[k]);
            key = (n << 4) | warp;   // n < 4096 -> fits; min key == min orig
        }
        const int wkey = __reduce_min_sync(0xffffffffu, key);

        if (key == wkey) {  // unique owner: prefetch coords, overlaps barrier
            int n = wkey >> 4;
            float ox = __ldg(p + 3 * n + 0);
            float oy = __ldg(p + 3 * n + 1);
            float oz = __ldg(p + 3 * n + 2);
            s_cc[t & 1][warp] = make_float4(ox, oy, oz, 0.0f);
        }
        if (lane == 0) { s_val[t & 1][warp] = wmax; s_key[t & 1][warp] = wkey; }
        __syncthreads();

        int vb = (lane < 16) ? s_val[t & 1][lane] : (int)0x80000000;
        int vk = (lane < 16) ? s_key[t & 1][lane] : 0x7fffffff;
        const int bmax = __reduce_max_sync(0xffffffffu, vb);
        int cand = (vb == bmax) ? vk : 0x7fffffff;
        const int kmin = __reduce_min_sync(0xffffffffu, cand);
        const int Iv = kmin >> 4, ww = kmin & 15;
        float4 cc = s_cc[t & 1][ww];    // uniform broadcast LDS.128
        cx = cc.x; cy = cc.y; cz = cc.z;
        if (tid == 0) g_fps[b * MCTR + t] = Iv;
    }
}

// ---------------------------------------------------------------------------
// 2) GEMM body (512 threads): pre[b][n][o] = sum_c feat[b][c][n] * W[o][c].
// ---------------------------------------------------------------------------
__device__ void gemm_body(const float* __restrict__ feat,
                          const float* __restrict__ W, int gid) {
    const int b    = gid >> 7;
    const int rest = gid & 127;
    const int o0   = (rest & 1) * 128;
    const int n0   = (rest >> 1) * 64;

    __shared__ float sF[32][66];
    __shared__ float sW[32][132];

    const int tid = threadIdx.x;
    const int tx = tid & 31;
    const int ty = tid >> 5;

    float acc[2][8];
#pragma unroll
    for (int i = 0; i < 2; i++)
#pragma unroll
        for (int j = 0; j < 8; j++) acc[i][j] = 0.f;

    const float* fb = feat + b * CIN * NPTS;

    for (int k0 = 0; k0 < CIN; k0 += 32) {
#pragma unroll
        for (int i = 0; i < 4; i++) {
            int e = tid + i * 512;
            sF[e >> 6][e & 63] = fb[(k0 + (e >> 6)) * NPTS + n0 + (e & 63)];
        }
#pragma unroll
        for (int i = 0; i < 8; i++) {
            int e = tid + i * 512;
            sW[e & 31][e >> 5] = W[(o0 + (e >> 5)) * CIN + k0 + (e & 31)];
        }
        __syncthreads();
#pragma unroll
        for (int c = 0; c < 32; c++) {
            float fv0 = sF[c][tx * 2 + 0];
            float fv1 = sF[c][tx * 2 + 1];
            float wv[8];
#pragma unroll
            for (int j = 0; j < 8; j++) wv[j] = sW[c][ty * 8 + j];
#pragma unroll
            for (int j = 0; j < 8; j++) {
                acc[0][j] += fv0 * wv[j];
                acc[1][j] += fv1 * wv[j];
            }
        }
        __syncthreads();
    }

    float* pb = g_pre + b * NPTS * COUT;
#pragma unroll
    for (int i = 0; i < 2; i++) {
        int n = n0 + tx * 2 + i;
#pragma unroll
        for (int j = 0; j < 8; j++)
            pb[n * COUT + o0 + ty * 8 + j] = acc[i][j];
    }
}

// ---------------------------------------------------------------------------
__global__ __launch_bounds__(512) void fused_fps_gemm_kernel(
    const float* __restrict__ xyz, const float* __restrict__ feat,
    const float* __restrict__ W) {
    if (blockIdx.x < BSZ) fps_body(xyz, blockIdx.x);
    else                  gemm_body(feat, W, blockIdx.x - BSZ);
}

// ---------------------------------------------------------------------------
// 3) Ball query: one warp per (b,m) center (unchanged, bit-exact).
// ---------------------------------------------------------------------------
__global__ __launch_bounds__(256) void ballquery_kernel(const float* __restrict__ xyz) {
    const int tid = threadIdx.x, lane = tid & 31, w = tid >> 5;
    const int gw = blockIdx.x * 8 + w;
    const int b = gw >> 10, m = gw & (MCTR - 1);
    const float* p = xyz + b * NPTS * 3;

    const int ci = g_fps[b * MCTR + m];
    const float cx = p[3 * ci + 0], cy = p[3 * ci + 1], cz = p[3 * ci + 2];
    const float R2 = 0.1024f;

    int cnt = 0, firstIdx = 0;
    int* dst = g_idx + (b * MCTR + m) * SSAMP;

    for (int c0 = 0; c0 < NPTS && cnt < SSAMP; c0 += 32) {
        int n = c0 + lane;
        float d = d2_rn(p[3 * n + 0], p[3 * n + 1], p[3 * n + 2], cx, cy, cz);
        bool in = d < R2;
        unsigned msk = __ballot_sync(0xffffffffu, in);
        if (cnt == 0 && msk) firstIdx = c0 + (__ffs(msk) - 1);
        if (in) {
            int pos = cnt + __popc(msk & ((1u << lane) - 1u));
            if (pos < SSAMP) dst[pos] = n;
        }
        cnt += __popc(msk);
    }
    for (int pos = cnt + lane; pos < SSAMP; pos += 32) dst[pos] = firstIdx;
}

// ---------------------------------------------------------------------------
// 4) Max-gather + folded BN/bias/ReLU (unchanged).
// ---------------------------------------------------------------------------
__global__ __launch_bounds__(64) void maxpool_kernel(
    const float* __restrict__ bconv, const float* __restrict__ gamma,
    const float* __restrict__ beta,  const float* __restrict__ rmean,
    const float* __restrict__ rvar,  float* __restrict__ out) {
    const int m = blockIdx.x, b = blockIdx.y, tid = threadIdx.x;

    __shared__ int soff[SSAMP];
    soff[tid] = g_idx[(b * MCTR + m) * SSAMP + tid] * COUT;
    __syncthreads();

    const float* pb = g_pre + b * NPTS * COUT + tid * 4;
    float4 mx = make_float4(-3.4e38f, -3.4e38f, -3.4e38f, -3.4e38f);
#pragma unroll 8
    for (int s = 0; s < SSAMP; s++) {
        const float4 v = *(const float4*)(pb + soff[s]);
        mx.x = fmaxf(mx.x, v.x); mx.y = fmaxf(mx.y, v.y);
        mx.z = fmaxf(mx.z, v.z); mx.w = fmaxf(mx.w, v.w);
    }

    const float4 bc = ((const float4*)bconv)[tid];
    const float4 gm = ((const float4*)gamma)[tid];
    const float4 bt = ((const float4*)beta )[tid];
    const float4 rm = ((const float4*)rmean)[tid];
    const float4 rv = ((const float4*)rvar )[tid];

    const int o = tid * 4;
    out[(b * COUT + o + 0) * MCTR + m] =
        fmaxf((mx.x + bc.x - rm.x) * (gm.x * rsqrtf(rv.x + 1e-5f)) + bt.x, 0.f);
    out[(b * COUT + o + 1) * MCTR + m] =
        fmaxf((mx.y + bc.y - rm.y) * (gm.y * rsqrtf(rv.y + 1e-5f)) + bt.y, 0.f);
    out[(b * COUT + o + 2) * MCTR + m] =
        fmaxf((mx.z + bc.z - rm.z) * (gm.z * rsqrtf(rv.z + 1e-5f)) + bt.z, 0.f);
    out[(b * COUT + o + 3) * MCTR + m] =
        fmaxf((mx.w + bc.w - rm.w) * (gm.w * rsqrtf(rv.w + 1e-5f)) + bt.w, 0.f);
}

// ---------------------------------------------------------------------------
extern "C" void kernel_launch(void* const* d_in, const int* in_sizes, int n_in,
                              void* d_out, int out_size) {
    const float* xyz  = (const float*)d_in[0];
    const float* feat = (const float*)d_in[1];
    const float* W    = (const float*)d_in[2];
    const float* bcv  = (const float*)d_in[3];
    const float* gm   = (const float*)d_in[4];
    const float* bt   = (const float*)d_in[5];
    const float* rm   = (const float*)d_in[6];
    const float* rv   = (const float*)d_in[7];
    float* out = (float*)d_out;

    const int gemm_blocks = (NPTS / 64) * (COUT / 128) * BSZ;  // 1024
    sort_kernel<<<BSZ, 512>>>(xyz);
    fused_fps_gemm_kernel<<<BSZ + gemm_blocks, 512>>>(xyz, feat, W);
    ballquery_kernel<<<(BSZ * MCTR) / 8, 256>>>(xyz);
    maxpool_kernel<<<dim3(MCTR, BSZ), 64>>>(bcv, gm, bt, rm, rv, out);
}